// round 4
// baseline (speedup 1.0000x reference)
#include <cuda_runtime.h>
#include <math.h>

#define N 8192
#define D 64
#define ALPHA 0.2f
#define NB 16384
#define SHIFT 18           // bucket = top 14 bits of order-flipped float key
#define NBLK 130
#define NTHR 1024
#define GSIZE (NBLK * NTHR)

// ---------------- scratch (device globals; no allocation allowed) -----------
__device__ float    g_h[N * D];        // projected features (2 MB)
__device__ float    g_hsT[D * N];      // h, sorted order, TRANSPOSED [d][k] (2 MB)
__device__ float    g_f1[N];
__device__ float    g_f2[N];
__device__ unsigned g_ukey[N];
__device__ int      g_hist[NB];
__device__ int      g_incl[NB];        // block-local inclusive scan of hist
__device__ int      g_btot[16];
__device__ int      g_start[NB + 1];
__device__ int      g_cursor[NB];
__device__ unsigned g_bkey[N];
__device__ int      g_bidx[N];
__device__ float    g_f2s[N];          // f2 sorted ascending
__device__ float    g_ehi[N];          // e^{f2s}
__device__ float    g_elo[N];          // e^{ALPHA*f2s}
__device__ int      g_p[N];            // per-row split point
__device__ float    g_c[N];            // per-row e^{(ALPHA-1) f1}
__device__ double   g_Phi[N * D];      // inclusive prefix of e^{f2} h, [k][d]
__device__ double   g_Plo[N * D];      // inclusive prefix of e^{a f2} h, [k][d]
__device__ double   g_pshi[N];
__device__ double   g_pslo[N];

// ---------------- software grid barrier -------------------------------------
__device__ unsigned g_bar_arrive = 0;
__device__ unsigned g_bar_gen    = 0;

__device__ __forceinline__ void gbar(unsigned& gen) {
    __syncthreads();
    if (threadIdx.x == 0) {
        __threadfence();
        unsigned my = gen;
        if (atomicAdd(&g_bar_arrive, 1) == NBLK - 1) {
            g_bar_arrive = 0;          // reset BEFORE release (ordered by fence)
            __threadfence();
            atomicAdd(&g_bar_gen, 1);
        } else {
            while (*(volatile unsigned*)&g_bar_gen == my) __nanosleep(32);
        }
        __threadfence();
        gen = my + 1;
    }
    __syncthreads();
}

// ---------------- the single persistent kernel ------------------------------
__global__ void __launch_bounds__(NTHR, 1) k_fused(
    const float* __restrict__ x,  const float* __restrict__ Wt,
    const float* __restrict__ a1, const float* __restrict__ b1,
    const float* __restrict__ a2, const float* __restrict__ b2,
    float* __restrict__ out)
{
    __shared__ float  sWt[D * D];      // 16 KB
    __shared__ float  sx[16 * D];      // 4 KB
    __shared__ float  sa1[D], sa2[D];
    __shared__ float  sred1[32], sred2[32];
    __shared__ int    sint[32];
    __shared__ double sdbl[32];

    const int t    = threadIdx.x;
    const int b    = blockIdx.x;
    const int gtid = b * NTHR + t;
    const int lane = t & 31, warp = t >> 5;
    unsigned gen = *(volatile unsigned*)&g_bar_gen;   // per-launch snapshot

    // ===== Phase A: projection h = x*Wt, scores f1/f2, key + histogram ======
    if (b < 128) {
        for (int i = t; i < D * D; i += NTHR) sWt[i] = Wt[i];
        if (t < D) { sa1[t] = a1[t]; sa2[t] = a2[t]; }
        const int r = t >> 6;          // 0..15 local row
        const int d = t & 63;
        for (int chunk = 0; chunk < 4; chunk++) {
            const int row0 = b * 64 + chunk * 16;
            __syncthreads();           // protect sx reuse (and sWt on chunk 0)
            for (int i = t; i < 16 * D; i += NTHR) sx[i] = x[row0 * D + i];
            __syncthreads();
            float h = 0.f;
            #pragma unroll
            for (int k = 0; k < D; k += 4) {
                float4 xv = *(const float4*)&sx[r * D + k];
                h = fmaf(xv.x, sWt[(k + 0) * D + d], h);
                h = fmaf(xv.y, sWt[(k + 1) * D + d], h);
                h = fmaf(xv.z, sWt[(k + 2) * D + d], h);
                h = fmaf(xv.w, sWt[(k + 3) * D + d], h);
            }
            g_h[(row0 + r) * D + d] = h;

            float p1 = h * sa1[d];
            float p2 = h * sa2[d];
            #pragma unroll
            for (int off = 16; off > 0; off >>= 1) {
                p1 += __shfl_down_sync(0xffffffffu, p1, off);
                p2 += __shfl_down_sync(0xffffffffu, p2, off);
            }
            if (lane == 0) { sred1[warp] = p1; sred2[warp] = p2; }
            __syncthreads();
            if (t < 16) {
                float f1  = sred1[2 * t] + sred1[2 * t + 1] + b1[0];
                float f2v = sred2[2 * t] + sred2[2 * t + 1] + b2[0];
                int row = row0 + t;
                g_f1[row] = f1;
                g_f2[row] = f2v;
                unsigned u = __float_as_uint(f2v);
                u ^= (u >> 31) ? 0xFFFFFFFFu : 0x80000000u;
                g_ukey[row] = u;
                atomicAdd(&g_hist[u >> SHIFT], 1);
            }
        }
    }
    gbar(gen);

    // ===== Phase B1: per-block inclusive scan of histogram (16 blocks) ======
    if (b < 16) {
        int i = b * NTHR + t;
        int v = g_hist[i];
        int s = v;
        #pragma unroll
        for (int off = 1; off < 32; off <<= 1) {
            int o = __shfl_up_sync(0xffffffffu, s, off);
            if (lane >= off) s += o;
        }
        if (lane == 31) sint[warp] = s;
        __syncthreads();
        if (t < 32) {
            int w2 = sint[t];
            #pragma unroll
            for (int off = 1; off < 32; off <<= 1) {
                int o = __shfl_up_sync(0xffffffffu, w2, off);
                if (t >= off) w2 += o;
            }
            sint[t] = w2;
        }
        __syncthreads();
        int incl = s + (warp ? sint[warp - 1] : 0);
        g_incl[i] = incl;
        if (t == NTHR - 1) g_btot[b] = incl;
    }
    gbar(gen);

    // ===== Phase B3: global offsets -> start/cursor =========================
    if (b < 16) {
        int off = 0;
        #pragma unroll
        for (int j = 0; j < 16; j++) if (j < b) off += g_btot[j];
        int i = b * NTHR + t;
        int excl = off + g_incl[i] - g_hist[i];
        g_start[i]  = excl;
        g_cursor[i] = excl;
    }
    if (b == 0 && t == 0) g_start[NB] = N;
    gbar(gen);

    // ===== Phase C: scatter into buckets ====================================
    if (gtid < N) {
        unsigned u = g_ukey[gtid];
        int pos = atomicAdd(&g_cursor[u >> SHIFT], 1);
        g_bkey[pos] = u;
        g_bidx[pos] = gtid;
    }
    gbar(gen);

    // ===== Phase D: rank within bucket + emit sorted arrays + transpose h ===
    //                 (spare threads re-zero the histogram for the next replay)
    if (gtid < N) {
        unsigned u = g_bkey[gtid];
        int i  = g_bidx[gtid];
        int bk = u >> SHIFT;
        int st = g_start[bk], en = g_start[bk + 1];
        int rank = st;
        for (int j = st; j < en; j++) {
            unsigned kj = g_bkey[j];
            rank += (kj < u) || (kj == u && g_bidx[j] < i);
        }
        float f2v = g_f2[i];
        g_f2s[rank] = f2v;
        g_ehi[rank] = expf(f2v);
        g_elo[rank] = expf(ALPHA * f2v);
        #pragma unroll
        for (int j = 0; j < D; j += 4) {
            float4 hv = *(const float4*)&g_h[i * D + j];
            g_hsT[(j + 0) * N + rank] = hv.x;
            g_hsT[(j + 1) * N + rank] = hv.y;
            g_hsT[(j + 2) * N + rank] = hv.z;
            g_hsT[(j + 3) * N + rank] = hv.w;
        }
    } else if (gtid - N < NB) {
        g_hist[gtid - N] = 0;
    }
    gbar(gen);

    // ===== Phase E: 130 inclusive fp64 scans (one per block) + psearch ======
    {
        bool scalar = (b >= 128);
        bool hi = (b < 64) || (b == 128);
        int dim = scalar ? 0 : (hi ? b : b - 64);
        const float* e    = hi ? g_ehi : g_elo;
        const float* hrow = g_hsT + (size_t)dim * N;

        int k0 = t * 8;
        double v[8];
        double run = 0.0;
        #pragma unroll
        for (int j = 0; j < 8; j++) {
            double val = (double)e[k0 + j];
            if (!scalar) val *= (double)hrow[k0 + j];
            run += val;
            v[j] = run;
        }
        double w = run;
        #pragma unroll
        for (int off = 1; off < 32; off <<= 1) {
            double o = __shfl_up_sync(0xffffffffu, w, off);
            if (lane >= off) w += o;
        }
        if (lane == 31) sdbl[warp] = w;
        __syncthreads();
        if (t < 32) {
            double x2 = sdbl[t];
            #pragma unroll
            for (int off = 1; off < 32; off <<= 1) {
                double o = __shfl_up_sync(0xffffffffu, x2, off);
                if (t >= off) x2 += o;
            }
            sdbl[t] = x2;
        }
        __syncthreads();
        double base = (w - run) + (warp ? sdbl[warp - 1] : 0.0);

        if (scalar) {
            double* o = hi ? g_pshi : g_pslo;
            #pragma unroll
            for (int j = 0; j < 8; j++) o[k0 + j] = base + v[j];
        } else {
            double* o = hi ? g_Phi : g_Plo;
            #pragma unroll
            for (int j = 0; j < 8; j++) o[(k0 + j) * D + dim] = base + v[j];
        }

        // per-row binary search (independent of scan stores; idle-lane work)
        if (t < 64) {
            int row = b * 64 + t;
            if (row < N) {
                float f1 = g_f1[row];
                float tt = -f1;
                int lo = 0, hi2 = N;           // p = #{ f2s <= -f1 }
                while (lo < hi2) {
                    int mid = (lo + hi2) >> 1;
                    if (g_f2s[mid] <= tt) lo = mid + 1; else hi2 = mid;
                }
                g_p[row] = lo;
                g_c[row] = expf((ALPHA - 1.0f) * f1);
            }
        }
    }
    gbar(gen);

    // ===== Phase G: combine + ELU ===========================================
    for (int idx = gtid; idx < N * D; idx += GSIZE) {
        int row = idx >> 6, d = idx & 63;
        int   p = g_p[row];
        float c = g_c[row];
        double num = g_Phi[(N - 1) * D + d];
        double den = g_pshi[N - 1];
        if (p > 0) {
            num -= g_Phi[(p - 1) * D + d];
            den -= g_pshi[p - 1];
            num += (double)c * g_Plo[(p - 1) * D + d];
            den += (double)c * g_pslo[p - 1];
        }
        float v = (float)num / (float)den;
        out[idx] = (v > 0.f) ? v : expm1f(v);
    }
}

// ---------------- launch ----------------------------------------------------
extern "C" void kernel_launch(void* const* d_in, const int* in_sizes, int n_in,
                              void* d_out, int out_size) {
    const float* x  = (const float*)d_in[0];
    const float* Wt = (const float*)d_in[1];
    const float* a1 = (const float*)d_in[2];
    const float* b1 = (const float*)d_in[3];
    const float* a2 = (const float*)d_in[4];
    const float* b2 = (const float*)d_in[5];
    float* out = (float*)d_out;

    k_fused<<<NBLK, NTHR>>>(x, Wt, a1, b1, a2, b2, out);
}

// round 5
// speedup vs baseline: 1.1606x; 1.1606x over previous
#include <cuda_runtime.h>
#include <math.h>

#define N 8192
#define D 64
#define ALPHA 0.2f
#define NB 16384
#define SHIFT 18           // bucket = top 14 bits of order-flipped float key
#define NBLK 130
#define NTHR 1024
#define GSIZE (NBLK * NTHR)

// ---------------- scratch (device globals; no allocation allowed) -----------
__device__ float    g_h[N * D];        // projected features (2 MB)
__device__ float    g_hsT[D * N];      // h, sorted order, TRANSPOSED [d][k] (2 MB)
__device__ float    g_f1[N];
__device__ float    g_f2[N];
__device__ unsigned g_ukey[N];
__device__ int      g_hist[NB];
__device__ int      g_incl[NB];        // block-local inclusive scan of hist
__device__ int      g_btot[16];
__device__ int      g_start[NB + 1];
__device__ int      g_cursor[NB];
__device__ unsigned g_bkey[N];
__device__ int      g_bidx[N];
__device__ float    g_f2s[N];          // f2 sorted ascending
__device__ int      g_ord[N];          // sorted position -> original index
__device__ float    g_ehi[N];          // e^{f2s}
__device__ float    g_elo[N];          // e^{ALPHA*f2s}
__device__ int      g_p[N];            // per-row split point
__device__ float    g_c[N];            // per-row e^{(ALPHA-1) f1}
__device__ double   g_Phi[N * D];      // inclusive prefix of e^{f2} h, [k][d]
__device__ double   g_Plo[N * D];      // inclusive prefix of e^{a f2} h, [k][d]
__device__ double   g_pshi[N];
__device__ double   g_pslo[N];

// ---------------- software grid barrier -------------------------------------
__device__ unsigned g_bar_arrive = 0;
__device__ unsigned g_bar_gen    = 0;

__device__ __forceinline__ void gbar(unsigned& gen) {
    __syncthreads();
    if (threadIdx.x == 0) {
        __threadfence();
        unsigned my = gen;
        if (atomicAdd(&g_bar_arrive, 1) == NBLK - 1) {
            g_bar_arrive = 0;          // reset BEFORE release (ordered by fence)
            __threadfence();
            atomicAdd(&g_bar_gen, 1);
        } else {
            while (*(volatile unsigned*)&g_bar_gen == my) __nanosleep(32);
        }
        __threadfence();
        gen = my + 1;
    }
    __syncthreads();
}

// ---------------- the single persistent kernel ------------------------------
__global__ void __launch_bounds__(NTHR, 1) k_fused(
    const float* __restrict__ x,  const float* __restrict__ Wt,
    const float* __restrict__ a1, const float* __restrict__ b1,
    const float* __restrict__ a2, const float* __restrict__ b2,
    float* __restrict__ out)
{
    __shared__ float  sWt[D * D];      // 16 KB
    __shared__ float  sx[16 * D];      // 4 KB
    __shared__ float  sa1[D], sa2[D];
    __shared__ float  sred1[32], sred2[32];
    __shared__ int    sint[32];
    __shared__ double sdbl[32];

    const int t    = threadIdx.x;
    const int b    = blockIdx.x;
    const int gtid = b * NTHR + t;
    const int lane = t & 31, warp = t >> 5;
    unsigned gen = *(volatile unsigned*)&g_bar_gen;   // per-launch snapshot

    // ===== Phase A: projection h = x*Wt, scores f1/f2, key + histogram ======
    if (b < 128) {
        for (int i = t; i < D * D; i += NTHR) sWt[i] = Wt[i];
        if (t < D) { sa1[t] = a1[t]; sa2[t] = a2[t]; }
        const int r = t >> 6;          // 0..15 local row
        const int d = t & 63;
        for (int chunk = 0; chunk < 4; chunk++) {
            const int row0 = b * 64 + chunk * 16;
            __syncthreads();           // protect sx reuse (and sWt on chunk 0)
            for (int i = t; i < 16 * D; i += NTHR) sx[i] = x[row0 * D + i];
            __syncthreads();
            float h = 0.f;
            #pragma unroll
            for (int k = 0; k < D; k += 4) {
                float4 xv = *(const float4*)&sx[r * D + k];
                h = fmaf(xv.x, sWt[(k + 0) * D + d], h);
                h = fmaf(xv.y, sWt[(k + 1) * D + d], h);
                h = fmaf(xv.z, sWt[(k + 2) * D + d], h);
                h = fmaf(xv.w, sWt[(k + 3) * D + d], h);
            }
            g_h[(row0 + r) * D + d] = h;

            float p1 = h * sa1[d];
            float p2 = h * sa2[d];
            #pragma unroll
            for (int off = 16; off > 0; off >>= 1) {
                p1 += __shfl_down_sync(0xffffffffu, p1, off);
                p2 += __shfl_down_sync(0xffffffffu, p2, off);
            }
            if (lane == 0) { sred1[warp] = p1; sred2[warp] = p2; }
            __syncthreads();
            if (t < 16) {
                float f1  = sred1[2 * t] + sred1[2 * t + 1] + b1[0];
                float f2v = sred2[2 * t] + sred2[2 * t + 1] + b2[0];
                int row = row0 + t;
                g_f1[row] = f1;
                g_f2[row] = f2v;
                unsigned u = __float_as_uint(f2v);
                u ^= (u >> 31) ? 0xFFFFFFFFu : 0x80000000u;
                g_ukey[row] = u;
                atomicAdd(&g_hist[u >> SHIFT], 1);
            }
        }
    }
    gbar(gen);

    // ===== Phase B1: per-block inclusive scan of histogram (16 blocks) ======
    if (b < 16) {
        int i = b * NTHR + t;
        int v = g_hist[i];
        int s = v;
        #pragma unroll
        for (int off = 1; off < 32; off <<= 1) {
            int o = __shfl_up_sync(0xffffffffu, s, off);
            if (lane >= off) s += o;
        }
        if (lane == 31) sint[warp] = s;
        __syncthreads();
        if (t < 32) {
            int w2 = sint[t];
            #pragma unroll
            for (int off = 1; off < 32; off <<= 1) {
                int o = __shfl_up_sync(0xffffffffu, w2, off);
                if (t >= off) w2 += o;
            }
            sint[t] = w2;
        }
        __syncthreads();
        int incl = s + (warp ? sint[warp - 1] : 0);
        g_incl[i] = incl;
        if (t == NTHR - 1) g_btot[b] = incl;
    }
    gbar(gen);

    // ===== Phase B3: global offsets -> start/cursor =========================
    if (b < 16) {
        int off = 0;
        #pragma unroll
        for (int j = 0; j < 16; j++) if (j < b) off += g_btot[j];
        int i = b * NTHR + t;
        int excl = off + g_incl[i] - g_hist[i];
        g_start[i]  = excl;
        g_cursor[i] = excl;
    }
    if (b == 0 && t == 0) g_start[NB] = N;
    gbar(gen);

    // ===== Phase C: scatter into buckets; spare threads re-zero histogram ===
    if (gtid < N) {
        unsigned u = g_ukey[gtid];
        int pos = atomicAdd(&g_cursor[u >> SHIFT], 1);
        g_bkey[pos] = u;
        g_bidx[pos] = gtid;
    } else if (gtid - N < NB) {
        g_hist[gtid - N] = 0;
    }
    gbar(gen);

    // ===== Phase D: rank within bucket, 16 threads per element ==============
    {
        int el  = gtid >> 4;           // 0..8319
        int seg = gtid & 15;
        if (el < N) {
            unsigned u = g_bkey[el];
            int i  = g_bidx[el];
            int bk = u >> SHIFT;
            int st = g_start[bk], en = g_start[bk + 1];
            int rank = 0;
            for (int j = st + seg; j < en; j += 16) {
                unsigned kj = g_bkey[j];
                rank += (kj < u) || (kj == u && g_bidx[j] < i);
            }
            #pragma unroll
            for (int off = 8; off > 0; off >>= 1)
                rank += __shfl_down_sync(0xffffffffu, rank, off, 16);
            if (seg == 0) {
                rank += st;
                float f2v = g_f2[i];
                g_f2s[rank] = f2v;
                g_ord[rank] = i;
                g_ehi[rank] = expf(f2v);
                g_elo[rank] = expf(ALPHA * f2v);
            }
        }
    }
    gbar(gen);

    // ===== Phase D2: transpose h into sorted order, all blocks ==============
    // idx = d*N + k; consecutive threads -> consecutive k: coalesced stores,
    // scattered independent loads (high MLP), spread over 130 SMs.
    for (int idx = gtid; idx < N * D; idx += GSIZE) {
        int d = idx >> 13;
        int k = idx & (N - 1);
        g_hsT[idx] = g_h[g_ord[k] * D + d];
    }
    gbar(gen);

    // ===== Phase E: 130 inclusive fp64 scans (one per block) + psearch ======
    {
        bool scalar = (b >= 128);
        bool hi = (b < 64) || (b == 128);
        int dim = scalar ? 0 : (hi ? b : b - 64);
        const float* e    = hi ? g_ehi : g_elo;
        const float* hrow = g_hsT + (size_t)dim * N;

        int k0 = t * 8;
        double v[8];
        double run = 0.0;
        #pragma unroll
        for (int j = 0; j < 8; j++) {
            double val = (double)e[k0 + j];
            if (!scalar) val *= (double)hrow[k0 + j];
            run += val;
            v[j] = run;
        }
        double w = run;
        #pragma unroll
        for (int off = 1; off < 32; off <<= 1) {
            double o = __shfl_up_sync(0xffffffffu, w, off);
            if (lane >= off) w += o;
        }
        if (lane == 31) sdbl[warp] = w;
        __syncthreads();
        if (t < 32) {
            double x2 = sdbl[t];
            #pragma unroll
            for (int off = 1; off < 32; off <<= 1) {
                double o = __shfl_up_sync(0xffffffffu, x2, off);
                if (t >= off) x2 += o;
            }
            sdbl[t] = x2;
        }
        __syncthreads();
        double base = (w - run) + (warp ? sdbl[warp - 1] : 0.0);

        if (scalar) {
            double* o = hi ? g_pshi : g_pslo;
            #pragma unroll
            for (int j = 0; j < 8; j++) o[k0 + j] = base + v[j];
        } else {
            double* o = hi ? g_Phi : g_Plo;
            #pragma unroll
            for (int j = 0; j < 8; j++) o[(k0 + j) * D + dim] = base + v[j];
        }

        // per-row binary search (idle-lane work, independent of scan stores)
        if (t < 64) {
            int row = b * 64 + t;
            if (row < N) {
                float f1 = g_f1[row];
                float tt = -f1;
                int lo = 0, hi2 = N;           // p = #{ f2s <= -f1 }
                while (lo < hi2) {
                    int mid = (lo + hi2) >> 1;
                    if (g_f2s[mid] <= tt) lo = mid + 1; else hi2 = mid;
                }
                g_p[row] = lo;
                g_c[row] = expf((ALPHA - 1.0f) * f1);
            }
        }
    }
    gbar(gen);

    // ===== Phase G: combine + ELU ===========================================
    for (int idx = gtid; idx < N * D; idx += GSIZE) {
        int row = idx >> 6, d = idx & 63;
        int   p = g_p[row];
        float c = g_c[row];
        double num = g_Phi[(N - 1) * D + d];
        double den = g_pshi[N - 1];
        if (p > 0) {
            num -= g_Phi[(p - 1) * D + d];
            den -= g_pshi[p - 1];
            num += (double)c * g_Plo[(p - 1) * D + d];
            den += (double)c * g_pslo[p - 1];
        }
        float v = (float)num / (float)den;
        out[idx] = (v > 0.f) ? v : expm1f(v);
    }
}

// ---------------- launch ----------------------------------------------------
extern "C" void kernel_launch(void* const* d_in, const int* in_sizes, int n_in,
                              void* d_out, int out_size) {
    const float* x  = (const float*)d_in[0];
    const float* Wt = (const float*)d_in[1];
    const float* a1 = (const float*)d_in[2];
    const float* b1 = (const float*)d_in[3];
    const float* a2 = (const float*)d_in[4];
    const float* b2 = (const float*)d_in[5];
    float* out = (float*)d_out;

    k_fused<<<NBLK, NTHR>>>(x, Wt, a1, b1, a2, b2, out);
}